// round 14
// baseline (speedup 1.0000x reference)
#include <cuda_runtime.h>
#include <cstring>

namespace {
constexpr int   Bb     = 256;
constexpr int   Nn     = 128;
constexpr int   Mm     = 192;
constexpr int   PA     = 132;   // pitch: mult of 4 -> every row 16B aligned
constexpr int   PH     = 132;
constexpr int   PTT    = 130;   // TpT pitch: 130%32=2 -> conflict-free u64 col reads
constexpr float RHO    = 0.1f;
constexpr float SIGMA  = 1e-6f;
constexpr float ALPHA  = 1.6f;
constexpr int   NITERS = 400;
constexpr int   NT     = 512;

// shared memory layout (floats); offsets all mult of 4 (16B aligned)
constexpr int OFF_A   = 0;                  // 192*132 = 25344
constexpr int OFF_H   = OFF_A + Mm * PA;    // 128*132 = 16896
constexpr int OFF_TPT = OFF_H + Nn * PH;    // region 8448 (TpT 64*130; GJ snapshots)
constexpr int OFF_Q   = OFF_TPT + 8448;
constexpr int OFF_L   = OFF_Q + Nn;
constexpr int OFF_UB  = OFF_L + Mm;
constexpr int OFF_C   = OFF_UB + Mm;
constexpr int OFF_WT0 = OFF_C + Mm;         // transposed w double buffer: [8][24] floats
constexpr int OFF_WT1 = OFF_WT0 + 192;
constexpr int OFF_V   = OFF_WT1 + 192;
constexpr int OFF_G   = OFF_V + Mm;
constexpr int OFF_HV  = OFF_G + Nn;
constexpr int SMEM_FLOATS = OFF_HV + Nn;
static_assert(SMEM_FLOATS * 4 <= 227 * 1024, "");
}

typedef unsigned long long u64;

__device__ __forceinline__ u64 fma2(u64 a, u64 b, u64 c) {
    u64 d;
    asm("fma.rn.f32x2 %0, %1, %2, %3;" : "=l"(d) : "l"(a), "l"(b), "l"(c));
    return d;
}
__device__ __forceinline__ u64 splat2(float v) {
    u64 d; unsigned u = __float_as_uint(v);
    asm("mov.b64 %0, {%1, %1};" : "=l"(d) : "r"(u));
    return d;
}
__device__ __forceinline__ float hadd2(u64 p) {
    float2 f; memcpy(&f, &p, 8); return f.x + f.y;
}
__device__ __forceinline__ u64 pack2(float a, float b) {
    float2 f; f.x = a; f.y = b; u64 u; memcpy(&u, &f, 8); return u;
}
__device__ __forceinline__ void unpack2(u64 p, float& a, float& b) {
    float2 f; memcpy(&f, &p, 8); a = f.x; b = f.y;
}

extern __shared__ float smem[];

__global__ __launch_bounds__(NT, 1)
void osqp_admm_kernel(const float* __restrict__ gP,
                      const float* __restrict__ gq,
                      const float* __restrict__ gA,
                      const float* __restrict__ gl,
                      const float* __restrict__ gu,
                      float* __restrict__ gout)
{
    const int b   = blockIdx.x;
    const int tid = threadIdx.x;
    const int ty8 = tid >> 3;        // 0..63
    const int tx8 = tid & 7;         // 0..7

    float* sA   = smem + OFF_A;
    float* sH   = smem + OFF_H;
    float* sTpT = smem + OFF_TPT;
    float* sq   = smem + OFF_Q;
    float* sl   = smem + OFF_L;
    float* sub  = smem + OFF_UB;
    float* sc   = smem + OFF_C;
    float* swt  = smem + OFF_WT0;    // [2][192] transposed w
    float* sv   = smem + OFF_V;
    float* sg   = smem + OFF_G;
    float* sh   = smem + OFF_HV;

    // ------------------------------------------------------------------
    // Phase 0: load A (pitched), H = P + sigma*I, vectors; wT0 = 0
    // ------------------------------------------------------------------
    {
        const float* pA = gA + (size_t)b * Mm * Nn;
        for (int idx = tid; idx < Mm * Nn; idx += NT)
            sA[(idx >> 7) * PA + (idx & 127)] = pA[idx];

        const float* pP = gP + (size_t)b * Nn * Nn;
        for (int idx = tid; idx < Nn * Nn; idx += NT) {
            int i = idx >> 7, j = idx & 127;
            float v = pP[idx];
            if (i == j) v += SIGMA;
            sH[i * PH + j] = v;
        }
        for (int n = tid; n < Nn; n += NT) sq[n] = gq[(size_t)b * Nn + n];
        for (int m = tid; m < Mm; m += NT) {
            sl[m]  = gl[(size_t)b * Mm + m];
            sub[m] = gu[(size_t)b * Mm + m];
            swt[m] = 0.f;            // buffer 0 (zeros regardless of layout)
        }
    }
    __syncthreads();

    // ------------------------------------------------------------------
    // Phase 1: H += rho * A^T A   — packed over output-row pairs.
    // ------------------------------------------------------------------
    {
        const int ty1 = tid >> 5;    // 0..15
        const int tx1 = tid & 31;    // 0..31
        const int i0  = ty1 * 8;
        u64 acc[4][4];
        #pragma unroll
        for (int r = 0; r < 4; r++)
            #pragma unroll
            for (int c = 0; c < 4; c++) acc[r][c] = 0ull;

        #pragma unroll 2
        for (int m = 0; m < Mm; m++) {
            const float* row = sA + m * PA;
            const u64* ap = reinterpret_cast<const u64*>(row + i0);
            u64 p0 = ap[0], p1 = ap[1], p2 = ap[2], p3 = ap[3];
            u64 bs[4];
            #pragma unroll
            for (int c = 0; c < 4; c++) bs[c] = splat2(row[tx1 + 32 * c]);
            #pragma unroll
            for (int c = 0; c < 4; c++) {
                acc[0][c] = fma2(p0, bs[c], acc[0][c]);
                acc[1][c] = fma2(p1, bs[c], acc[1][c]);
                acc[2][c] = fma2(p2, bs[c], acc[2][c]);
                acc[3][c] = fma2(p3, bs[c], acc[3][c]);
            }
        }
        #pragma unroll
        for (int r = 0; r < 4; r++)
            #pragma unroll
            for (int c = 0; c < 4; c++) {
                float lo, hi; unpack2(acc[r][c], lo, hi);
                sH[(i0 + 2 * r)     * PH + tx1 + 32 * c] += RHO * lo;
                sH[(i0 + 2 * r + 1) * PH + tx1 + 32 * c] += RHO * hi;
            }
    }
    __syncthreads();

    // ------------------------------------------------------------------
    // Phase 2: in-place Gauss-Jordan inverse of H (SPD -> no pivoting)
    // ------------------------------------------------------------------
    {
        float* srk = sTpT;
        float* sck = sTpT + Nn;
        for (int k = 0; k < Nn; k++) {
            const float p = 1.0f / sH[k * PH + k];
            if (tid < Nn)            srk[tid] = sH[k * PH + tid];
            else if (tid < 2 * Nn)   sck[tid - Nn] = sH[(tid - Nn) * PH + k];
            __syncthreads();

            const int  j   = tid & 127;
            const int  i0  = (tid >> 7) * 32;
            const float rs = srk[j] * p;
            const bool jk  = (j == k);
            #pragma unroll 4
            for (int i = i0; i < i0 + 32; i++) {
                float hij = sH[i * PH + j];
                float f   = sck[i];
                float nv;
                if (i == k) nv = jk ? p : rs;
                else        nv = jk ? (-f * p) : fmaf(-f, rs, hij);
                sH[i * PH + j] = nv;
            }
            __syncthreads();
        }
    }
    // sH = M1 = H^{-1}

    // ------------------------------------------------------------------
    // Phase 3: h = M1*q ; c = -A*h
    // ------------------------------------------------------------------
    if (tid < Nn) {
        float a0 = 0.f, a1 = 0.f;
        const float* hp = sH + tid * PH;
        #pragma unroll 4
        for (int j = 0; j < Nn; j += 2) {
            a0 = fmaf(hp[j],     sq[j],     a0);
            a1 = fmaf(hp[j + 1], sq[j + 1], a1);
        }
        sh[tid] = a0 + a1;
    }
    __syncthreads();
    if (tid < Mm) {
        float a0 = 0.f, a1 = 0.f;
        const float* ap = sA + tid * PA;
        #pragma unroll 4
        for (int n = 0; n < Nn; n += 2) {
            a0 = fmaf(ap[n],     sh[n],     a0);
            a1 = fmaf(ap[n + 1], sh[n + 1], a1);
        }
        sc[tid] = -(a0 + a1);
    }
    __syncthreads();

    // ------------------------------------------------------------------
    // Phase 4: S = A*M1*A^T into registers rSp[3][12]:
    //   rSp[k][Jp] = pack(S[ty8+64k][2tx8+16Jp], S[ty8+64k][2tx8+16Jp+1])
    // 3 panels of 64 cols. Per panel p:
    //  (a) TpT[c][i] = sum_j M1[i][j]*A[64p+c][j]   (packed over j)
    //  (b) dots packed over i, cols c_local = 2tx8+16Jl+d (Jl<4, d<2)
    // ------------------------------------------------------------------
    u64 rSp[3][12];
    {
        const int ty3 = tid >> 4;    // 0..31 (rows i = ty3+32r)
        const int tx3 = tid & 15;
        #pragma unroll
        for (int p = 0; p < 3; p++) {
            // ---- (a) T panel (transposed store) ----
            u64 ta[4][4];
            #pragma unroll
            for (int r = 0; r < 4; r++)
                #pragma unroll
                for (int d = 0; d < 4; d++) ta[r][d] = 0ull;
            #pragma unroll 2
            for (int j = 0; j < Nn; j += 2) {
                u64 mp[4], an[4];
                #pragma unroll
                for (int r = 0; r < 4; r++)
                    mp[r] = *reinterpret_cast<const u64*>(sH + (ty3 + 32 * r) * PH + j);
                #pragma unroll
                for (int d = 0; d < 4; d++)
                    an[d] = *reinterpret_cast<const u64*>(sA + (64 * p + tx3 + 16 * d) * PA + j);
                #pragma unroll
                for (int r = 0; r < 4; r++)
                    #pragma unroll
                    for (int d = 0; d < 4; d++)
                        ta[r][d] = fma2(mp[r], an[d], ta[r][d]);
            }
            #pragma unroll
            for (int r = 0; r < 4; r++)
                #pragma unroll
                for (int d = 0; d < 4; d++)
                    sTpT[(tx3 + 16 * d) * PTT + (ty3 + 32 * r)] = hadd2(ta[r][d]);
            __syncthreads();

            // ---- (b) 3 rows x 8 panel-cols per thread ----
            u64 bacc[3][8];
            #pragma unroll
            for (int k = 0; k < 3; k++)
                #pragma unroll
                for (int c = 0; c < 8; c++) bacc[k][c] = 0ull;
            #pragma unroll 2
            for (int i = 0; i < Nn; i += 2) {
                u64 apk[3], tpd[8];
                #pragma unroll
                for (int k = 0; k < 3; k++)
                    apk[k] = *reinterpret_cast<const u64*>(sA + (ty8 + 64 * k) * PA + i);
                #pragma unroll
                for (int c = 0; c < 8; c++) {
                    const int cl = 2 * tx8 + 16 * (c >> 1) + (c & 1);
                    tpd[c] = *reinterpret_cast<const u64*>(sTpT + cl * PTT + i);
                }
                #pragma unroll
                for (int k = 0; k < 3; k++)
                    #pragma unroll
                    for (int c = 0; c < 8; c++)
                        bacc[k][c] = fma2(apk[k], tpd[c], bacc[k][c]);
            }
            #pragma unroll
            for (int k = 0; k < 3; k++)
                #pragma unroll
                for (int Jl = 0; Jl < 4; Jl++)
                    rSp[k][4 * p + Jl] = pack2(hadd2(bacc[k][2 * Jl]),
                                               hadd2(bacc[k][2 * Jl + 1]));
            __syncthreads();
        }
    }

    // ------------------------------------------------------------------
    // Phase 5: owner-register state (thread (ty8, tx8<3) owns m=ty8+64*tx8)
    // ------------------------------------------------------------------
    const int  mown = ty8 + 64 * tx8;
    const bool own  = (tx8 < 3);
    float rz = 0.f, ry = 0.f, ru = 0.f, rw = 0.f;
    float rl = 0.f, rub = 0.f, rc = 0.f;
    int   widx = 0;
    if (own) {
        rl = sl[mown]; rub = sub[mown]; rc = sc[mown];
        widx = ((mown & 15) >> 1) * 24 + 2 * (mown >> 4) + (mown & 1);
    }
    __syncthreads();

    // ------------------------------------------------------------------
    // Phase 6: 400 iterations; one packed matvec, 8-wide butterfly,
    // one barrier each. wT layout: pair Jp of lane tx8 at floats
    // [tx8*24 + 2*Jp, +1], i.e. w[2*tx8+16*Jp+d].
    // ------------------------------------------------------------------
    for (int it = 0; it < NITERS; it++) {
        const float* wb = swt + (it & 1) * 192 + tx8 * 24;
        const ulonglong2* wq = reinterpret_cast<const ulonglong2*>(wb);
        ulonglong2 q0 = wq[0], q1 = wq[1], q2 = wq[2],
                   q3 = wq[3], q4 = wq[4], q5 = wq[5];
        u64 a0 = 0ull, a1 = 0ull, a2 = 0ull;
        a0 = fma2(rSp[0][0],  q0.x, a0); a1 = fma2(rSp[1][0],  q0.x, a1); a2 = fma2(rSp[2][0],  q0.x, a2);
        a0 = fma2(rSp[0][1],  q0.y, a0); a1 = fma2(rSp[1][1],  q0.y, a1); a2 = fma2(rSp[2][1],  q0.y, a2);
        a0 = fma2(rSp[0][2],  q1.x, a0); a1 = fma2(rSp[1][2],  q1.x, a1); a2 = fma2(rSp[2][2],  q1.x, a2);
        a0 = fma2(rSp[0][3],  q1.y, a0); a1 = fma2(rSp[1][3],  q1.y, a1); a2 = fma2(rSp[2][3],  q1.y, a2);
        a0 = fma2(rSp[0][4],  q2.x, a0); a1 = fma2(rSp[1][4],  q2.x, a1); a2 = fma2(rSp[2][4],  q2.x, a2);
        a0 = fma2(rSp[0][5],  q2.y, a0); a1 = fma2(rSp[1][5],  q2.y, a1); a2 = fma2(rSp[2][5],  q2.y, a2);
        a0 = fma2(rSp[0][6],  q3.x, a0); a1 = fma2(rSp[1][6],  q3.x, a1); a2 = fma2(rSp[2][6],  q3.x, a2);
        a0 = fma2(rSp[0][7],  q3.y, a0); a1 = fma2(rSp[1][7],  q3.y, a1); a2 = fma2(rSp[2][7],  q3.y, a2);
        a0 = fma2(rSp[0][8],  q4.x, a0); a1 = fma2(rSp[1][8],  q4.x, a1); a2 = fma2(rSp[2][8],  q4.x, a2);
        a0 = fma2(rSp[0][9],  q4.y, a0); a1 = fma2(rSp[1][9],  q4.y, a1); a2 = fma2(rSp[2][9],  q4.y, a2);
        a0 = fma2(rSp[0][10], q5.x, a0); a1 = fma2(rSp[1][10], q5.x, a1); a2 = fma2(rSp[2][10], q5.x, a2);
        a0 = fma2(rSp[0][11], q5.y, a0); a1 = fma2(rSp[1][11], q5.y, a1); a2 = fma2(rSp[2][11], q5.y, a2);

        float s0 = hadd2(a0), s1 = hadd2(a1), s2 = hadd2(a2);
        #pragma unroll
        for (int s = 4; s >= 1; s >>= 1) {
            s0 += __shfl_xor_sync(0xffffffffu, s0, s, 8);
            s1 += __shfl_xor_sync(0xffffffffu, s1, s, 8);
            s2 += __shfl_xor_sync(0xffffffffu, s2, s, 8);
        }
        if (own) {
            float zt = s0;                    // explicit select (no dyn index)
            if (tx8 == 1) zt = s1;
            if (tx8 == 2) zt = s2;
            zt += rc;
            ru = fmaf(1.0f - ALPHA, ru, ALPHA * rw);       // v-recursion
            const float zc = fmaf(ALPHA, zt, (1.0f - ALPHA) * rz);
            const float vv = fmaf(ry, 1.0f / RHO, zc);
            const float zn = fminf(fmaxf(vv, rl), rub);
            ry = fmaf(RHO, zc - zn, ry);
            rz = zn;
            rw = fmaf(RHO, zn, -ry);
            swt[((it + 1) & 1) * 192 + widx] = rw;
        }
        __syncthreads();
    }

    // ------------------------------------------------------------------
    // Phase 7: epilogue  x = M1*(A^T v - q)
    // ------------------------------------------------------------------
    if (own) sv[mown] = ru;
    __syncthreads();
    if (tid < Nn) {
        float a0 = 0.f, a1 = 0.f;
        #pragma unroll 4
        for (int m = 0; m < Mm; m += 2) {
            a0 = fmaf(sA[m * PA + tid],       sv[m],     a0);
            a1 = fmaf(sA[(m + 1) * PA + tid], sv[m + 1], a1);
        }
        sg[tid] = (a0 + a1) - sq[tid];
    }
    __syncthreads();
    if (tid < Nn) {
        float a0 = 0.f, a1 = 0.f;
        const float* hp = sH + tid * PH;
        #pragma unroll 4
        for (int j = 0; j < Nn; j += 2) {
            a0 = fmaf(hp[j],     sg[j],     a0);
            a1 = fmaf(hp[j + 1], sg[j + 1], a1);
        }
        gout[(size_t)b * Nn + tid] = a0 + a1;
    }
}

extern "C" void kernel_launch(void* const* d_in, const int* in_sizes, int n_in,
                              void* d_out, int out_size)
{
    const float* P = (const float*)d_in[0];   // (256,128,128)
    const float* q = (const float*)d_in[1];   // (256,128)
    const float* A = (const float*)d_in[2];   // (256,192,128)
    const float* l = (const float*)d_in[3];   // (256,192)
    const float* u = (const float*)d_in[4];   // (256,192)
    float* out = (float*)d_out;               // (256,128)

    const int smem_bytes = SMEM_FLOATS * (int)sizeof(float);
    // Unconditional (no static guard). Not stream-ordered -> capture-legal; idempotent.
    cudaFuncSetAttribute(osqp_admm_kernel,
                         cudaFuncAttributeMaxDynamicSharedMemorySize,
                         smem_bytes);
    osqp_admm_kernel<<<Bb, NT, smem_bytes>>>(P, q, A, l, u, out);
}

// round 15
// speedup vs baseline: 1.0688x; 1.0688x over previous
#include <cuda_runtime.h>
#include <cstring>

namespace {
constexpr int   Bb     = 256;
constexpr int   Nn     = 128;
constexpr int   Mm     = 192;
constexpr int   PA     = 132;   // pitch: mult of 4 -> every row 16B aligned
constexpr int   PH     = 132;
constexpr int   PTT    = 130;   // TpT pitch: 130%32=2 -> conflict-free u64 col reads
constexpr float RHO    = 0.1f;
constexpr float SIGMA  = 1e-6f;
constexpr float ALPHA  = 1.6f;
constexpr int   NITERS = 400;
constexpr int   NT     = 1024;  // 32 warps -> 8 per SMSP

// shared memory layout (floats); offsets all mult of 4 (16B aligned)
constexpr int OFF_A   = 0;                  // 192*132 = 25344
constexpr int OFF_H   = OFF_A + Mm * PA;    // 128*132 = 16896
constexpr int OFF_TPT = OFF_H + Nn * PH;    // 8448 region (TpT 64*130; GJ snapshots)
constexpr int OFF_Q   = OFF_TPT + 8448;
constexpr int OFF_L   = OFF_Q + Nn;
constexpr int OFF_UB  = OFF_L + Mm;
constexpr int OFF_C   = OFF_UB + Mm;
constexpr int OFF_WT0 = OFF_C + Mm;         // transposed w double buffer: [16][12]
constexpr int OFF_WT1 = OFF_WT0 + 192;
constexpr int OFF_V   = OFF_WT1 + 192;
constexpr int OFF_G   = OFF_V + Mm;
constexpr int OFF_HV  = OFF_G + Nn;
constexpr int SMEM_FLOATS = OFF_HV + Nn;
static_assert(SMEM_FLOATS * 4 <= 227 * 1024, "");
}

typedef unsigned long long u64;

__device__ __forceinline__ u64 fma2(u64 a, u64 b, u64 c) {
    u64 d;
    asm("fma.rn.f32x2 %0, %1, %2, %3;" : "=l"(d) : "l"(a), "l"(b), "l"(c));
    return d;
}
__device__ __forceinline__ u64 splat2(float v) {
    u64 d; unsigned u = __float_as_uint(v);
    asm("mov.b64 %0, {%1, %1};" : "=l"(d) : "r"(u));
    return d;
}
__device__ __forceinline__ float hadd2(u64 p) {
    float2 f; memcpy(&f, &p, 8); return f.x + f.y;
}
__device__ __forceinline__ u64 pack2(float a, float b) {
    float2 f; f.x = a; f.y = b; u64 u; memcpy(&u, &f, 8); return u;
}
__device__ __forceinline__ void unpack2(u64 p, float& a, float& b) {
    float2 f; memcpy(&f, &p, 8); a = f.x; b = f.y;
}

extern __shared__ float smem[];

__global__ __launch_bounds__(NT, 1)
void osqp_admm_kernel(const float* __restrict__ gP,
                      const float* __restrict__ gq,
                      const float* __restrict__ gA,
                      const float* __restrict__ gl,
                      const float* __restrict__ gu,
                      float* __restrict__ gout)
{
    const int b   = blockIdx.x;
    const int tid = threadIdx.x;
    const int ty  = tid >> 4;        // 0..63
    const int tx  = tid & 15;        // 0..15

    float* sA   = smem + OFF_A;
    float* sH   = smem + OFF_H;
    float* sTpT = smem + OFF_TPT;
    float* sq   = smem + OFF_Q;
    float* sl   = smem + OFF_L;
    float* sub  = smem + OFF_UB;
    float* sc   = smem + OFF_C;
    float* swt  = smem + OFF_WT0;    // [2][192] transposed w
    float* sv   = smem + OFF_V;
    float* sg   = smem + OFF_G;
    float* sh   = smem + OFF_HV;

    // ------------------------------------------------------------------
    // Phase 0: load A (pitched), H = P + sigma*I, vectors; wT0 = 0
    // ------------------------------------------------------------------
    {
        const float* pA = gA + (size_t)b * Mm * Nn;
        for (int idx = tid; idx < Mm * Nn; idx += NT)
            sA[(idx >> 7) * PA + (idx & 127)] = pA[idx];

        const float* pP = gP + (size_t)b * Nn * Nn;
        for (int idx = tid; idx < Nn * Nn; idx += NT) {
            int i = idx >> 7, j = idx & 127;
            float v = pP[idx];
            if (i == j) v += SIGMA;
            sH[i * PH + j] = v;
        }
        if (tid < Nn) sq[tid] = gq[(size_t)b * Nn + tid];
        if (tid < Mm) {
            sl[tid]  = gl[(size_t)b * Mm + tid];
            sub[tid] = gu[(size_t)b * Mm + tid];
            swt[tid] = 0.f;          // buffer 0
        }
    }
    __syncthreads();

    // ------------------------------------------------------------------
    // Phase 1: H += rho * A^T A  — 1024 threads, 2 packed row-pairs x 4 cols
    // ------------------------------------------------------------------
    {
        const int ty1 = tid >> 5;    // 0..31
        const int tx1 = tid & 31;    // 0..31
        const int i0  = ty1 * 4;     // rows i0..i0+3 (2 packed pairs)
        u64 acc[2][4];
        #pragma unroll
        for (int r = 0; r < 2; r++)
            #pragma unroll
            for (int c = 0; c < 4; c++) acc[r][c] = 0ull;

        #pragma unroll 2
        for (int m = 0; m < Mm; m++) {
            const float* row = sA + m * PA;
            const u64* ap = reinterpret_cast<const u64*>(row + i0);
            u64 p0 = ap[0], p1 = ap[1];
            u64 bs[4];
            #pragma unroll
            for (int c = 0; c < 4; c++) bs[c] = splat2(row[tx1 + 32 * c]);
            #pragma unroll
            for (int c = 0; c < 4; c++) {
                acc[0][c] = fma2(p0, bs[c], acc[0][c]);
                acc[1][c] = fma2(p1, bs[c], acc[1][c]);
            }
        }
        #pragma unroll
        for (int r = 0; r < 2; r++)
            #pragma unroll
            for (int c = 0; c < 4; c++) {
                float lo, hi; unpack2(acc[r][c], lo, hi);
                sH[(i0 + 2 * r)     * PH + tx1 + 32 * c] += RHO * lo;
                sH[(i0 + 2 * r + 1) * PH + tx1 + 32 * c] += RHO * hi;
            }
    }
    __syncthreads();

    // ------------------------------------------------------------------
    // Phase 2: in-place Gauss-Jordan inverse of H (SPD -> no pivoting)
    // 1024 threads: column j = tid&127, slice s = tid>>7 -> 16 rows each.
    // ------------------------------------------------------------------
    {
        float* srk = sTpT;
        float* sck = sTpT + Nn;
        for (int k = 0; k < Nn; k++) {
            const float p = 1.0f / sH[k * PH + k];
            if (tid < Nn)            srk[tid] = sH[k * PH + tid];
            else if (tid < 2 * Nn)   sck[tid - Nn] = sH[(tid - Nn) * PH + k];
            __syncthreads();

            const int  j   = tid & 127;
            const int  i0  = (tid >> 7) * 16;
            const float rs = srk[j] * p;
            const bool jk  = (j == k);
            #pragma unroll 4
            for (int i = i0; i < i0 + 16; i++) {
                float hij = sH[i * PH + j];
                float f   = sck[i];
                float nv;
                if (i == k) nv = jk ? p : rs;
                else        nv = jk ? (-f * p) : fmaf(-f, rs, hij);
                sH[i * PH + j] = nv;
            }
            __syncthreads();
        }
    }
    // sH = M1 = H^{-1}

    // ------------------------------------------------------------------
    // Phase 3: h = M1*q ; c = -A*h
    // ------------------------------------------------------------------
    if (tid < Nn) {
        float a0 = 0.f, a1 = 0.f;
        const float* hp = sH + tid * PH;
        #pragma unroll 4
        for (int j = 0; j < Nn; j += 2) {
            a0 = fmaf(hp[j],     sq[j],     a0);
            a1 = fmaf(hp[j + 1], sq[j + 1], a1);
        }
        sh[tid] = a0 + a1;
    }
    __syncthreads();
    if (tid < Mm) {
        float a0 = 0.f, a1 = 0.f;
        const float* ap = sA + tid * PA;
        #pragma unroll 4
        for (int n = 0; n < Nn; n += 2) {
            a0 = fmaf(ap[n],     sh[n],     a0);
            a1 = fmaf(ap[n + 1], sh[n + 1], a1);
        }
        sc[tid] = -(a0 + a1);
    }
    __syncthreads();

    // ------------------------------------------------------------------
    // Phase 4: S = A*M1*A^T into packed registers rSp[3][6]:
    //   rSp[k][Jp] = pack(S[ty+64k][tx+16*2Jp], S[ty+64k][tx+16*(2Jp+1)])
    // 3 panels of 64 cols. Per panel p (cols 64p..64p+63; J = 4p..4p+3):
    //  (a) TpT[c][i] = sum_j M1[i][j]*A[64p+c][j]   (packed over j)
    //  (b) dot over i for cols tx+16Jl (Jl<4), packed over i
    // ------------------------------------------------------------------
    u64 rSp[3][6];
    {
        #pragma unroll
        for (int p = 0; p < 3; p++) {
            // ---- (a) T panel (transposed store): 2 rows x 4 cols/thread ----
            u64 ta[2][4];
            #pragma unroll
            for (int r = 0; r < 2; r++)
                #pragma unroll
                for (int d = 0; d < 4; d++) ta[r][d] = 0ull;
            #pragma unroll 2
            for (int j = 0; j < Nn; j += 2) {
                u64 mp[2], an[4];
                #pragma unroll
                for (int r = 0; r < 2; r++)
                    mp[r] = *reinterpret_cast<const u64*>(sH + (ty + 64 * r) * PH + j);
                #pragma unroll
                for (int d = 0; d < 4; d++)
                    an[d] = *reinterpret_cast<const u64*>(sA + (64 * p + tx + 16 * d) * PA + j);
                #pragma unroll
                for (int r = 0; r < 2; r++)
                    #pragma unroll
                    for (int d = 0; d < 4; d++)
                        ta[r][d] = fma2(mp[r], an[d], ta[r][d]);
            }
            #pragma unroll
            for (int r = 0; r < 2; r++)
                #pragma unroll
                for (int d = 0; d < 4; d++)
                    sTpT[(tx + 16 * d) * PTT + (ty + 64 * r)] = hadd2(ta[r][d]);
            __syncthreads();

            // ---- (b) 3 rows x 4 panel-cols per thread ----
            u64 bacc[3][4];
            #pragma unroll
            for (int k = 0; k < 3; k++)
                #pragma unroll
                for (int d = 0; d < 4; d++) bacc[k][d] = 0ull;
            #pragma unroll 2
            for (int i = 0; i < Nn; i += 2) {
                u64 apk[3], tpd[4];
                #pragma unroll
                for (int k = 0; k < 3; k++)
                    apk[k] = *reinterpret_cast<const u64*>(sA + (ty + 64 * k) * PA + i);
                #pragma unroll
                for (int d = 0; d < 4; d++)
                    tpd[d] = *reinterpret_cast<const u64*>(sTpT + (tx + 16 * d) * PTT + i);
                #pragma unroll
                for (int k = 0; k < 3; k++)
                    #pragma unroll
                    for (int d = 0; d < 4; d++)
                        bacc[k][d] = fma2(apk[k], tpd[d], bacc[k][d]);
            }
            #pragma unroll
            for (int k = 0; k < 3; k++)
                #pragma unroll
                for (int jp = 0; jp < 2; jp++)
                    rSp[k][2 * p + jp] = pack2(hadd2(bacc[k][2 * jp]),
                                               hadd2(bacc[k][2 * jp + 1]));
            __syncthreads();
        }
    }

    // ------------------------------------------------------------------
    // Phase 5: owner-register state (thread (ty, tx<3) owns m = ty+64*tx)
    // ------------------------------------------------------------------
    const int  mown = ty + 64 * tx;
    const bool own  = (tx < 3);
    float rz = 0.f, ry = 0.f, ru = 0.f, rw = 0.f;
    float rl = 0.f, rub = 0.f, rc = 0.f;
    int   widx = 0;
    if (own) {
        rl = sl[mown]; rub = sub[mown]; rc = sc[mown];
        widx = (mown & 15) * 12 + (mown >> 4);   // wT[t][J] at t*12+J, m=t+16J
    }
    __syncthreads();

    // ------------------------------------------------------------------
    // Phase 6: 400 iterations; packed matvec + 16-wide butterfly + 1 barrier.
    // thread's 12 w values (w[tx+16J], J<12) contiguous at swt[buf*192+tx*12].
    // ------------------------------------------------------------------
    for (int it = 0; it < NITERS; it++) {
        const ulonglong2* wq =
            reinterpret_cast<const ulonglong2*>(swt + (it & 1) * 192 + tx * 12);
        ulonglong2 q0 = wq[0], q1 = wq[1], q2 = wq[2];
        u64 a0 = 0ull, a1 = 0ull, a2 = 0ull;
        a0 = fma2(rSp[0][0], q0.x, a0); a1 = fma2(rSp[1][0], q0.x, a1); a2 = fma2(rSp[2][0], q0.x, a2);
        a0 = fma2(rSp[0][1], q0.y, a0); a1 = fma2(rSp[1][1], q0.y, a1); a2 = fma2(rSp[2][1], q0.y, a2);
        a0 = fma2(rSp[0][2], q1.x, a0); a1 = fma2(rSp[1][2], q1.x, a1); a2 = fma2(rSp[2][2], q1.x, a2);
        a0 = fma2(rSp[0][3], q1.y, a0); a1 = fma2(rSp[1][3], q1.y, a1); a2 = fma2(rSp[2][3], q1.y, a2);
        a0 = fma2(rSp[0][4], q2.x, a0); a1 = fma2(rSp[1][4], q2.x, a1); a2 = fma2(rSp[2][4], q2.x, a2);
        a0 = fma2(rSp[0][5], q2.y, a0); a1 = fma2(rSp[1][5], q2.y, a1); a2 = fma2(rSp[2][5], q2.y, a2);

        float s0 = hadd2(a0), s1 = hadd2(a1), s2 = hadd2(a2);
        #pragma unroll
        for (int s = 8; s >= 1; s >>= 1) {
            s0 += __shfl_xor_sync(0xffffffffu, s0, s, 16);
            s1 += __shfl_xor_sync(0xffffffffu, s1, s, 16);
            s2 += __shfl_xor_sync(0xffffffffu, s2, s, 16);
        }
        if (own) {
            float zt = s0;                    // explicit select (no dyn index)
            if (tx == 1) zt = s1;
            if (tx == 2) zt = s2;
            zt += rc;
            ru = fmaf(1.0f - ALPHA, ru, ALPHA * rw);       // v-recursion
            const float zc = fmaf(ALPHA, zt, (1.0f - ALPHA) * rz);
            const float vv = fmaf(ry, 1.0f / RHO, zc);
            const float zn = fminf(fmaxf(vv, rl), rub);
            ry = fmaf(RHO, zc - zn, ry);
            rz = zn;
            rw = fmaf(RHO, zn, -ry);
            swt[((it + 1) & 1) * 192 + widx] = rw;
        }
        __syncthreads();
    }

    // ------------------------------------------------------------------
    // Phase 7: epilogue  x = M1*(A^T v - q)
    // ------------------------------------------------------------------
    if (own) sv[mown] = ru;
    __syncthreads();
    if (tid < Nn) {
        float a0 = 0.f, a1 = 0.f;
        #pragma unroll 4
        for (int m = 0; m < Mm; m += 2) {
            a0 = fmaf(sA[m * PA + tid],       sv[m],     a0);
            a1 = fmaf(sA[(m + 1) * PA + tid], sv[m + 1], a1);
        }
        sg[tid] = (a0 + a1) - sq[tid];
    }
    __syncthreads();
    if (tid < Nn) {
        float a0 = 0.f, a1 = 0.f;
        const float* hp = sH + tid * PH;
        #pragma unroll 4
        for (int j = 0; j < Nn; j += 2) {
            a0 = fmaf(hp[j],     sg[j],     a0);
            a1 = fmaf(hp[j + 1], sg[j + 1], a1);
        }
        gout[(size_t)b * Nn + tid] = a0 + a1;
    }
}

extern "C" void kernel_launch(void* const* d_in, const int* in_sizes, int n_in,
                              void* d_out, int out_size)
{
    const float* P = (const float*)d_in[0];   // (256,128,128)
    const float* q = (const float*)d_in[1];   // (256,128)
    const float* A = (const float*)d_in[2];   // (256,192,128)
    const float* l = (const float*)d_in[3];   // (256,192)
    const float* u = (const float*)d_in[4];   // (256,192)
    float* out = (float*)d_out;               // (256,128)

    const int smem_bytes = SMEM_FLOATS * (int)sizeof(float);
    // Unconditional (no static guard). Not stream-ordered -> capture-legal; idempotent.
    cudaFuncSetAttribute(osqp_admm_kernel,
                         cudaFuncAttributeMaxDynamicSharedMemorySize,
                         smem_bytes);
    osqp_admm_kernel<<<Bb, NT, smem_bytes>>>(P, q, A, l, u, out);
}